// round 3
// baseline (speedup 1.0000x reference)
#include <cuda_runtime.h>
#include <math.h>

// ---------------------------------------------------------------------------
// Fused per-graph GNN: 5x TAGConv(K=2) + ReLU + gated softmax pooling.
// One CTA per graph (5000 CTAs, 256 threads). All features in shared memory.
//
// R3: - weights repacked per-thread-interleaved (prep kernel) so each thread's
//       column-pair slabs load with 1-2 vector LDGs, no predication.
//     - 3 CTAs/SM via launch_bounds(256,3); float2 activation loads in the
//       3-slab layers to fit the register budget.
//     - fp32x2 packed FMA (fma.rn.f32x2) throughout the GEMM.
// ---------------------------------------------------------------------------

#define NODES   100
#define EDGES   400
#define NTHR    256
#define ST      76      // feature row stride in floats (multiple of 4)
#define ROWSPAD 112     // 16 thread-rows * 7 rows each

typedef unsigned long long ull;

__device__ __forceinline__ ull ffma2(ull a, ull b, ull c) {
    ull d;
    asm("fma.rn.f32x2 %0, %1, %2, %3;" : "=l"(d) : "l"(a), "l"(b), "l"(c));
    return d;
}
__device__ __forceinline__ ull pack2(float x, float y) {
    ull d;
    asm("mov.b64 %0, {%1, %2};" : "=l"(d) : "f"(x), "f"(y));
    return d;
}
__device__ __forceinline__ void unpack2(ull v, float& x, float& y) {
    asm("mov.b64 {%0, %1}, %2;" : "=f"(x), "=f"(y) : "l"(v));
}

// ---- interleaved padded weight scratch ------------------------------------
// Layer l, pass p, k-row k: row of RW floats. Thread tcol owns CH=RW/16
// floats at [tcol*CH, (tcol+1)*CH): SLABS column-pairs then zero pad.
// Pair s of thread t covers output cols c = 2*(16*s + t), c+1.
// RW = 128 for SLABS=3 (L0,L1), 64 for SLABS=2 (L2..L4).
// sizes (floats): L0 3*76*128=29184, L1 3*72*128=27648, L2 3*68*64=13056,
//                 L3 3*60*64=11520, L4 3*56*64=10752  -> total 92160
__device__ float g_Wpad[92160];

__global__ void prep_weights(const float* W0, const float* W1, const float* W2,
                             const float* W3, const float* W4) {
    const int DIN[5]   = {74, 70, 65, 60, 55};
    const int DINP[5]  = {76, 72, 68, 60, 56};
    const int DOUT[5]  = {70, 65, 60, 55, 37};
    const int RW[5]    = {128, 128, 64, 64, 64};
    const int SLABS[5] = {3, 3, 2, 2, 2};
    const int OFF[6]   = {0, 29184, 56832, 69888, 81408, 92160};
    const float* Ws[5] = {W0, W1, W2, W3, W4};

    for (int idx = blockIdx.x * blockDim.x + threadIdx.x; idx < 92160;
         idx += gridDim.x * blockDim.x) {
        int l = 0;
        while (idx >= OFF[l + 1]) l++;
        int rel = idx - OFF[l];
        int psz = DINP[l] * RW[l];
        int pass = rel / psz;
        int r2   = rel - pass * psz;
        int k    = r2 / RW[l];
        int slot = r2 - k * RW[l];
        int CH   = RW[l] / 16;
        int t    = slot / CH;
        int u    = slot - t * CH;
        int s    = u >> 1;
        int lane = u & 1;
        int c    = 2 * (16 * s + t) + lane;
        float v = 0.f;
        if (s < SLABS[l] && k < DIN[l] && c < DOUT[l])
            v = Ws[l][(pass * DIN[l] + k) * DOUT[l] + c];
        g_Wpad[idx] = v;
    }
}

struct SmemLayout {
    float buf0[ROWSPAD * ST];
    float buf1[ROWSPAD * ST];
    float norm[128];
    float red[128];
    float gate[128];
    int   rowptr[104];
    int   cnt[128];
    unsigned short csr[EDGES];
};

// ---- propagation over padded width ----------------------------------------
template <int DINP>
__device__ __forceinline__ void prop(const float* __restrict__ in,
                                     float* __restrict__ outb,
                                     const float* __restrict__ nrm,
                                     const int* __restrict__ rowptr,
                                     const unsigned short* __restrict__ csr,
                                     int tid) {
    constexpr int NQ = DINP / 4;
    for (int task = tid; task < NODES * NQ; task += NTHR) {
        int v  = task / NQ;
        int q  = task - v * NQ;
        int c0 = q * 4;
        float4 acc = make_float4(0.f, 0.f, 0.f, 0.f);
        int e0 = rowptr[v], e1 = rowptr[v + 1];
        for (int e = e0; e < e1; e++) {
            int s = csr[e];
            float f = nrm[s];
            float4 r = *reinterpret_cast<const float4*>(in + s * ST + c0);
            acc.x += f * r.x; acc.y += f * r.y;
            acc.z += f * r.z; acc.w += f * r.w;
        }
        float nv = nrm[v];
        acc.x *= nv; acc.y *= nv; acc.z *= nv; acc.w *= nv;
        *reinterpret_cast<float4*>(outb + v * ST + c0) = acc;
    }
}

// ---- GEMM pass, 2 slabs (RW=64): one LDG.128 per k ------------------------
template <int DINP>
__device__ __forceinline__ void gemm_pass2(ull acc[7][2],
                                           const float* __restrict__ H,
                                           const float* __restrict__ Wp,
                                           int trow, int tcol) {
    const float* hb = H + trow * 7 * ST;
    const float* wb = Wp + tcol * 4;
#pragma unroll 2
    for (int k0 = 0; k0 < DINP; k0 += 4) {
        float4 a4[7];
#pragma unroll
        for (int i = 0; i < 7; i++)
            a4[i] = *reinterpret_cast<const float4*>(hb + i * ST + k0);
#pragma unroll
        for (int kk = 0; kk < 4; kk++) {
            ulonglong2 w = __ldg(reinterpret_cast<const ulonglong2*>(
                wb + (k0 + kk) * 64));
#pragma unroll
            for (int i = 0; i < 7; i++) {
                float av = (kk == 0) ? a4[i].x : (kk == 1) ? a4[i].y
                         : (kk == 2) ? a4[i].z : a4[i].w;
                ull aa = pack2(av, av);
                acc[i][0] = ffma2(aa, w.x, acc[i][0]);
                acc[i][1] = ffma2(aa, w.y, acc[i][1]);
            }
        }
    }
}

// ---- GEMM pass, 3 slabs (RW=128): LDG.128 + LDG.64 per k ------------------
template <int DINP>
__device__ __forceinline__ void gemm_pass3(ull acc[7][3],
                                           const float* __restrict__ H,
                                           const float* __restrict__ Wp,
                                           int trow, int tcol) {
    const float* hb = H + trow * 7 * ST;
    const float* wb = Wp + tcol * 8;
#pragma unroll 2
    for (int k0 = 0; k0 < DINP; k0 += 2) {
        float2 a2[7];
#pragma unroll
        for (int i = 0; i < 7; i++)
            a2[i] = *reinterpret_cast<const float2*>(hb + i * ST + k0);
#pragma unroll
        for (int kk = 0; kk < 2; kk++) {
            const float* wrow = wb + (k0 + kk) * 128;
            ulonglong2 w01 = __ldg(reinterpret_cast<const ulonglong2*>(wrow));
            ull        w2  = __ldg(reinterpret_cast<const ull*>(wrow + 4));
#pragma unroll
            for (int i = 0; i < 7; i++) {
                float av = (kk == 0) ? a2[i].x : a2[i].y;
                ull aa = pack2(av, av);
                acc[i][0] = ffma2(aa, w01.x, acc[i][0]);
                acc[i][1] = ffma2(aa, w01.y, acc[i][1]);
                acc[i][2] = ffma2(aa, w2,    acc[i][2]);
            }
        }
    }
}

// ---- one TAGConv layer ------------------------------------------------------
// STOREP = padded width expected by the NEXT consumer (mult of 4); cols
// [DOUT, STOREP) are written as zeros, cols >= STOREP untouched (stay zero).
template <int DINP, int DOUT, int STOREP, int SLABS>
__device__ __forceinline__ void layer(float* bufIn, float* bufOut,
                                      const float* __restrict__ Wp,
                                      const float* __restrict__ B,
                                      SmemLayout* sm, int tid) {
    constexpr int PSZ = DINP * (SLABS == 3 ? 128 : 64);
    int trow = tid >> 4;
    int tcol = tid & 15;

    // U = A h -> bufOut
    prop<DINP>(bufIn, bufOut, sm->norm, sm->rowptr, sm->csr, tid);
    __syncthreads();

    ull acc[7][SLABS];
#pragma unroll
    for (int i = 0; i < 7; i++)
#pragma unroll
        for (int s = 0; s < SLABS; s++) acc[i][s] = 0ull;

    if (SLABS == 3) {
        gemm_pass3<DINP>((ull(*)[3])acc, bufIn,  Wp,           trow, tcol);
        gemm_pass3<DINP>((ull(*)[3])acc, bufOut, Wp + PSZ,     trow, tcol);
    } else {
        gemm_pass2<DINP>((ull(*)[2])acc, bufIn,  Wp,           trow, tcol);
        gemm_pass2<DINP>((ull(*)[2])acc, bufOut, Wp + PSZ,     trow, tcol);
    }
    __syncthreads();

    // V = A U -> bufIn (h dead)
    prop<DINP>(bufOut, bufIn, sm->norm, sm->rowptr, sm->csr, tid);
    __syncthreads();

    if (SLABS == 3)
        gemm_pass3<DINP>((ull(*)[3])acc, bufIn, Wp + 2 * PSZ, trow, tcol);
    else
        gemm_pass2<DINP>((ull(*)[2])acc, bufIn, Wp + 2 * PSZ, trow, tcol);
    __syncthreads();

    // epilogue: bias + relu -> bufOut; zero pad cols [DOUT, STOREP)
#pragma unroll
    for (int s = 0; s < SLABS; s++) {
        int c = 2 * (s * 16 + tcol);
        if (c < STOREP) {
            float b0 = (c     < DOUT) ? __ldg(B + c)     : 0.f;
            float b1 = (c + 1 < DOUT) ? __ldg(B + c + 1) : 0.f;
#pragma unroll
            for (int i = 0; i < 7; i++) {
                int r = trow * 7 + i;
                if (r < NODES) {
                    float lo, hi;
                    unpack2(acc[i][s], lo, hi);
                    float v0 = (c     < DOUT) ? fmaxf(lo + b0, 0.f) : 0.f;
                    float v1 = (c + 1 < DOUT) ? fmaxf(hi + b1, 0.f) : 0.f;
                    *reinterpret_cast<float2*>(bufOut + r * ST + c) =
                        make_float2(v0, v1);
                }
            }
        }
    }
    __syncthreads();
}

__global__ void __launch_bounds__(NTHR, 3)
gnn_fused_kernel(const float* __restrict__ x,
                 const int* __restrict__ src,
                 const int* __restrict__ dst,
                 const float* __restrict__ b0, const float* __restrict__ b1,
                 const float* __restrict__ b2, const float* __restrict__ b3,
                 const float* __restrict__ b4,
                 const float* __restrict__ gw, const float* __restrict__ gb,
                 float* __restrict__ out) {
    extern __shared__ char smem_raw[];
    SmemLayout* sm = reinterpret_cast<SmemLayout*>(smem_raw);
    const int tid = threadIdx.x;
    const int g   = blockIdx.x;

    float* A = sm->buf0;
    float* B = sm->buf1;

    // ---- zero both feature buffers (pad invariant), then load x
    {
        float4* z = reinterpret_cast<float4*>(sm->buf0);
        const int nq = 2 * ROWSPAD * ST / 4;   // buf0+buf1 contiguous
        for (int i = tid; i < nq; i += NTHR)
            z[i] = make_float4(0.f, 0.f, 0.f, 0.f);
    }
    if (tid < 128) sm->cnt[tid] = 0;
    __syncthreads();
    {
        const float* xg = x + (size_t)g * (NODES * 74);
        for (int idx = tid; idx < NODES * 74; idx += NTHR) {
            int v = idx / 74;
            int c = idx - v * 74;
            A[v * ST + c] = xg[idx];
        }
    }

    // ---- per-graph CSR (by dst) + norm
    const int* srcg = src + g * EDGES;
    const int* dstg = dst + g * EDGES;
    const int base = g * NODES;
    for (int e = tid; e < EDGES; e += NTHR) {
        int dl = dstg[e] - base;
        atomicAdd(&sm->cnt[dl], 1);
    }
    __syncthreads();
    if (tid < NODES)
        sm->norm[tid] = rsqrtf(fmaxf((float)sm->cnt[tid], 1.f));
    for (int off = 1; off < 128; off <<= 1) {       // inclusive scan
        int t = 0;
        if (tid < 128 && tid >= off) t = sm->cnt[tid - off];
        __syncthreads();
        if (tid < 128 && tid >= off) sm->cnt[tid] += t;
        __syncthreads();
    }
    if (tid == 0) sm->rowptr[0] = 0;
    if (tid < NODES) sm->rowptr[tid + 1] = sm->cnt[tid];
    __syncthreads();
    if (tid < NODES) sm->cnt[tid] = sm->rowptr[tid];
    __syncthreads();
    for (int e = tid; e < EDGES; e += NTHR) {
        int sl = srcg[e] - base;
        int dl = dstg[e] - base;
        int pos = atomicAdd(&sm->cnt[dl], 1);
        sm->csr[pos] = (unsigned short)sl;
    }
    __syncthreads();

    // ---- 5 TAGConv layers      DINP DOUT STOREP SLABS   Wpad offset
    layer<76, 70, 72, 3>(A, B, g_Wpad +     0, b0, sm, tid);
    layer<72, 65, 68, 3>(B, A, g_Wpad + 29184, b1, sm, tid);
    layer<68, 60, 60, 2>(A, B, g_Wpad + 56832, b2, sm, tid);
    layer<60, 55, 56, 2>(B, A, g_Wpad + 69888, b3, sm, tid);
    layer<56, 37, 40, 2>(A, B, g_Wpad + 81408, b4, sm, tid);
    float* H = B;   // final features: 100 x 37

    // ---- gate = H @ gate_w + gate_b ; softmax over graph; pooled sum
    float gval = -1e30f;
    if (tid < NODES) {
        float s = __ldg(gb);
#pragma unroll
        for (int c = 0; c < 37; c++)
            s += H[tid * ST + c] * __ldg(gw + c);
        sm->gate[tid] = s;
        gval = s;
    }
    if (tid < 128) sm->red[tid] = gval;
    __syncthreads();
    for (int s = 64; s > 0; s >>= 1) {
        if (tid < s) sm->red[tid] = fmaxf(sm->red[tid], sm->red[tid + s]);
        __syncthreads();
    }
    float gmax = sm->red[0];
    __syncthreads();

    float ev = 0.f;
    if (tid < NODES) {
        ev = expf(sm->gate[tid] - gmax);
        sm->gate[tid] = ev;
    }
    if (tid < 128) sm->red[tid] = ev;
    __syncthreads();
    for (int s = 64; s > 0; s >>= 1) {
        if (tid < s) sm->red[tid] += sm->red[tid + s];
        __syncthreads();
    }
    float Z = sm->red[0];

    if (tid < 37) {
        float a = 0.f;
        for (int v = 0; v < NODES; v++)
            a += sm->gate[v] * H[v * ST + tid];
        out[g * 37 + tid] = a / Z;
    }
}

extern "C" void kernel_launch(void* const* d_in, const int* in_sizes, int n_in,
                              void* d_out, int out_size) {
    const float* x   = (const float*)d_in[0];
    const int*   src = (const int*)d_in[1];
    const int*   dst = (const int*)d_in[2];
    const float* W0 = (const float*)d_in[4];
    const float* b0 = (const float*)d_in[5];
    const float* W1 = (const float*)d_in[6];
    const float* b1 = (const float*)d_in[7];
    const float* W2 = (const float*)d_in[8];
    const float* b2 = (const float*)d_in[9];
    const float* W3 = (const float*)d_in[10];
    const float* b3 = (const float*)d_in[11];
    const float* W4 = (const float*)d_in[12];
    const float* b4 = (const float*)d_in[13];
    const float* gw = (const float*)d_in[14];
    const float* gb = (const float*)d_in[15];
    float* out = (float*)d_out;

    prep_weights<<<90, 256>>>(W0, W1, W2, W3, W4);

    const int smem_bytes = (int)sizeof(SmemLayout);
    cudaFuncSetAttribute(gnn_fused_kernel,
                         cudaFuncAttributeMaxDynamicSharedMemorySize,
                         smem_bytes);
    gnn_fused_kernel<<<5000, NTHR, smem_bytes>>>(
        x, src, dst,
        b0, b1, b2, b3, b4,
        gw, gb, out);
}

// round 4
// speedup vs baseline: 2.2971x; 2.2971x over previous
#include <cuda_runtime.h>
#include <math.h>
#include <stdint.h>

// ---------------------------------------------------------------------------
// Fused per-graph GNN: 5x TAGConv(K=2) + ReLU + gated softmax pooling.
// One CTA per graph (5000 CTAs, 256 threads). All features in shared memory.
//
// R4: GEMMs on tensor cores via mma.sync.m16n8k8 tf32 with 3xTF32
//     (hi/lo split) error compensation. 8 warps = 8 M-tiles of 16 rows.
//     Weights pre-split into tf32 hi/lo and packed in B-fragment order by a
//     prep kernel -> one LDG.128 per (ktile,ntile), broadcast across warps.
// ---------------------------------------------------------------------------

#define NODES   100
#define EDGES   400
#define NTHR    256
#define ST      84      // smem row stride (floats): stride 84 mod 32 = 20 -> 8-row conflict-free
#define MROWS   128     // 8 m-tiles * 16

typedef unsigned long long ull;

__device__ __forceinline__ uint32_t f2tf32(float f) {
    uint32_t u;
    asm("cvt.rna.tf32.f32 %0, %1;" : "=r"(u) : "f"(f));
    return u;
}

__device__ __forceinline__ void mma_tf32(float c[4], const uint32_t a[4],
                                         uint32_t b0, uint32_t b1) {
    asm("mma.sync.aligned.m16n8k8.row.col.f32.tf32.tf32.f32 "
        "{%0,%1,%2,%3}, {%4,%5,%6,%7}, {%8,%9}, {%0,%1,%2,%3};"
        : "+f"(c[0]), "+f"(c[1]), "+f"(c[2]), "+f"(c[3])
        : "r"(a[0]), "r"(a[1]), "r"(a[2]), "r"(a[3]), "r"(b0), "r"(b1));
}

// ---- packed hi/lo weights in B-fragment order -----------------------------
// Layer l, pass p, ktile kt, ntile nt -> block of 128 floats:
//   lane*4 + {b0_hi, b1_hi, b0_lo, b1_lo}
// where b0 = W[k = kt*8 + lane%4,     col = nt*8 + lane/4]
//       b1 = W[k = kt*8 + lane%4 + 4, col = nt*8 + lane/4]
// KT = {10,9,9,8,7}, NT = {9,9,8,7,5}; per-layer floats = 3*KT*NT*128
// sizes: 34560, 31104, 27648, 21504, 13440 -> total 128256 floats
__device__ float g_Wpad[128256];

__global__ void prep_weights(const float* W0, const float* W1, const float* W2,
                             const float* W3, const float* W4) {
    const int DIN[5]  = {74, 70, 65, 60, 55};
    const int DOUT[5] = {70, 65, 60, 55, 37};
    const int KT[5]   = {10, 9, 9, 8, 7};
    const int NT[5]   = {9, 9, 8, 7, 5};
    const int OFF[6]  = {0, 34560, 65664, 93312, 114816, 128256};
    const float* Ws[5] = {W0, W1, W2, W3, W4};

    for (int idx = blockIdx.x * blockDim.x + threadIdx.x; idx < 128256;
         idx += gridDim.x * blockDim.x) {
        int l = 0;
        while (idx >= OFF[l + 1]) l++;
        int rel   = idx - OFF[l];
        int block = rel >> 7;
        int within = rel & 127;
        int lane = within >> 2;
        int j    = within & 3;          // 0:b0hi 1:b1hi 2:b0lo 3:b1lo
        int pnb  = KT[l] * NT[l];
        int p    = block / pnb;
        int r    = block - p * pnb;
        int kt   = r / NT[l];
        int nt   = r - kt * NT[l];
        int krow = (lane & 3) + ((j & 1) ? 4 : 0);
        int col  = nt * 8 + (lane >> 2);
        int k    = kt * 8 + krow;
        float w = 0.f;
        if (k < DIN[l] && col < DOUT[l])
            w = Ws[l][(p * DIN[l] + k) * DOUT[l] + col];
        uint32_t hi = f2tf32(w);
        float res;
        if (j < 2) {
            res = __uint_as_float(hi);
        } else {
            float lo = w - __uint_as_float(hi);
            res = __uint_as_float(f2tf32(lo));
        }
        g_Wpad[idx] = res;
    }
}

struct SmemLayout {
    float buf0[MROWS * ST];
    float buf1[MROWS * ST];
    float norm[128];
    float red[128];
    float gate[128];
    int   rowptr[104];
    int   cnt[128];
    unsigned short csr[EDGES];
};

// ---- propagation over padded width (pad cols zero in -> zero out) ---------
template <int DINP>
__device__ __forceinline__ void prop(const float* __restrict__ in,
                                     float* __restrict__ outb,
                                     const float* __restrict__ nrm,
                                     const int* __restrict__ rowptr,
                                     const unsigned short* __restrict__ csr,
                                     int tid) {
    constexpr int NQ = DINP / 4;
    for (int task = tid; task < NODES * NQ; task += NTHR) {
        int v  = task / NQ;
        int q  = task - v * NQ;
        int c0 = q * 4;
        float4 acc = make_float4(0.f, 0.f, 0.f, 0.f);
        int e0 = rowptr[v], e1 = rowptr[v + 1];
        for (int e = e0; e < e1; e++) {
            int s = csr[e];
            float f = nrm[s];
            float4 r = *reinterpret_cast<const float4*>(in + s * ST + c0);
            acc.x += f * r.x; acc.y += f * r.y;
            acc.z += f * r.z; acc.w += f * r.w;
        }
        float nv = nrm[v];
        acc.x *= nv; acc.y *= nv; acc.z *= nv; acc.w *= nv;
        *reinterpret_cast<float4*>(outb + v * ST + c0) = acc;
    }
}

// ---- one GEMM pass on tensor cores (3xTF32) -------------------------------
template <int KT, int NT>
__device__ __forceinline__ void gemm_mma(float C[NT][4],
                                         const float* __restrict__ H,
                                         const float* __restrict__ Wp,
                                         int wid, int lane) {
    const float* hb = H + (wid * 16 + (lane >> 2)) * ST + (lane & 3);
#pragma unroll
    for (int kt = 0; kt < KT; kt++) {
        float a0 = hb[kt * 8];
        float a1 = hb[kt * 8 + 8 * ST];
        float a2 = hb[kt * 8 + 4];
        float a3 = hb[kt * 8 + 4 + 8 * ST];
        uint32_t ahi[4], alo[4];
        ahi[0] = f2tf32(a0); ahi[1] = f2tf32(a1);
        ahi[2] = f2tf32(a2); ahi[3] = f2tf32(a3);
        alo[0] = f2tf32(a0 - __uint_as_float(ahi[0]));
        alo[1] = f2tf32(a1 - __uint_as_float(ahi[1]));
        alo[2] = f2tf32(a2 - __uint_as_float(ahi[2]));
        alo[3] = f2tf32(a3 - __uint_as_float(ahi[3]));
        const float4* wrow = reinterpret_cast<const float4*>(Wp) +
                             (size_t)kt * NT * 32 + lane;
#pragma unroll
        for (int nt = 0; nt < NT; nt++) {
            float4 w = __ldg(wrow + nt * 32);
            uint32_t bh0 = __float_as_uint(w.x);
            uint32_t bh1 = __float_as_uint(w.y);
            uint32_t bl0 = __float_as_uint(w.z);
            uint32_t bl1 = __float_as_uint(w.w);
            mma_tf32(C[nt], ahi, bh0, bh1);
            mma_tf32(C[nt], ahi, bl0, bl1);
            mma_tf32(C[nt], alo, bh0, bh1);
        }
    }
}

// ---- one TAGConv layer ----------------------------------------------------
template <int KT, int NT, int DOUT>
__device__ __forceinline__ void layer(float* bufIn, float* bufOut,
                                      const float* __restrict__ Wp,
                                      const float* __restrict__ B,
                                      SmemLayout* sm, int tid) {
    constexpr int DINP = KT * 8;
    constexpr int PSZ  = KT * NT * 128;
    int wid  = tid >> 5;
    int lane = tid & 31;

    // U = A h -> bufOut
    prop<DINP>(bufIn, bufOut, sm->norm, sm->rowptr, sm->csr, tid);
    __syncthreads();

    float C[NT][4];
#pragma unroll
    for (int nt = 0; nt < NT; nt++)
#pragma unroll
        for (int i = 0; i < 4; i++) C[nt][i] = 0.f;

    gemm_mma<KT, NT>(C, bufIn,  Wp,       wid, lane);   // h @ Wa
    gemm_mma<KT, NT>(C, bufOut, Wp + PSZ, wid, lane);   // U @ Wb
    __syncthreads();

    // V = A U -> bufIn (h dead)
    prop<DINP>(bufOut, bufIn, sm->norm, sm->rowptr, sm->csr, tid);
    __syncthreads();

    gemm_mma<KT, NT>(C, bufIn, Wp + 2 * PSZ, wid, lane); // V @ Wc

    // epilogue: bias + relu -> bufOut (only conflicts with own pass usage)
    int r0 = wid * 16 + (lane >> 2);
    int cb = 2 * (lane & 3);
#pragma unroll
    for (int nt = 0; nt < NT; nt++) {
        int c = nt * 8 + cb;
        float b0v = (c     < DOUT) ? __ldg(B + c)     : 0.f;
        float b1v = (c + 1 < DOUT) ? __ldg(B + c + 1) : 0.f;
        float v0 = (c     < DOUT) ? fmaxf(C[nt][0] + b0v, 0.f) : 0.f;
        float v1 = (c + 1 < DOUT) ? fmaxf(C[nt][1] + b1v, 0.f) : 0.f;
        if (r0 < NODES)
            *reinterpret_cast<float2*>(bufOut + r0 * ST + c) =
                make_float2(v0, v1);
        float v2 = (c     < DOUT) ? fmaxf(C[nt][2] + b0v, 0.f) : 0.f;
        float v3 = (c + 1 < DOUT) ? fmaxf(C[nt][3] + b1v, 0.f) : 0.f;
        if (r0 + 8 < NODES)
            *reinterpret_cast<float2*>(bufOut + (r0 + 8) * ST + c) =
                make_float2(v2, v3);
    }
    __syncthreads();
}

__global__ void __launch_bounds__(NTHR, 2)
gnn_fused_kernel(const float* __restrict__ x,
                 const int* __restrict__ src,
                 const int* __restrict__ dst,
                 const float* __restrict__ b0, const float* __restrict__ b1,
                 const float* __restrict__ b2, const float* __restrict__ b3,
                 const float* __restrict__ b4,
                 const float* __restrict__ gw, const float* __restrict__ gb,
                 float* __restrict__ out) {
    extern __shared__ char smem_raw[];
    SmemLayout* sm = reinterpret_cast<SmemLayout*>(smem_raw);
    const int tid = threadIdx.x;
    const int g   = blockIdx.x;

    float* A = sm->buf0;
    float* B = sm->buf1;

    // ---- zero both feature buffers (pad invariant), then load x
    {
        float4* z = reinterpret_cast<float4*>(sm->buf0);
        const int nq = 2 * MROWS * ST / 4;   // buf0+buf1 contiguous
        for (int i = tid; i < nq; i += NTHR)
            z[i] = make_float4(0.f, 0.f, 0.f, 0.f);
    }
    if (tid < 128) sm->cnt[tid] = 0;
    __syncthreads();
    {
        const float* xg = x + (size_t)g * (NODES * 74);
        for (int idx = tid; idx < NODES * 74; idx += NTHR) {
            int v = idx / 74;
            int c = idx - v * 74;
            A[v * ST + c] = xg[idx];
        }
    }

    // ---- per-graph CSR (by dst) + norm
    const int* srcg = src + g * EDGES;
    const int* dstg = dst + g * EDGES;
    const int base = g * NODES;
    for (int e = tid; e < EDGES; e += NTHR) {
        int dl = dstg[e] - base;
        atomicAdd(&sm->cnt[dl], 1);
    }
    __syncthreads();
    if (tid < NODES)
        sm->norm[tid] = rsqrtf(fmaxf((float)sm->cnt[tid], 1.f));
    for (int off = 1; off < 128; off <<= 1) {       // inclusive scan
        int t = 0;
        if (tid < 128 && tid >= off) t = sm->cnt[tid - off];
        __syncthreads();
        if (tid < 128 && tid >= off) sm->cnt[tid] += t;
        __syncthreads();
    }
    if (tid == 0) sm->rowptr[0] = 0;
    if (tid < NODES) sm->rowptr[tid + 1] = sm->cnt[tid];
    __syncthreads();
    if (tid < NODES) sm->cnt[tid] = sm->rowptr[tid];
    __syncthreads();
    for (int e = tid; e < EDGES; e += NTHR) {
        int sl = srcg[e] - base;
        int dl = dstg[e] - base;
        int pos = atomicAdd(&sm->cnt[dl], 1);
        sm->csr[pos] = (unsigned short)sl;
    }
    __syncthreads();

    // ---- 5 TAGConv layers       KT NT DOUT          Wpad offset
    layer<10, 9, 70>(A, B, g_Wpad +      0, b0, sm, tid);
    layer< 9, 9, 65>(B, A, g_Wpad +  34560, b1, sm, tid);
    layer< 9, 8, 60>(A, B, g_Wpad +  65664, b2, sm, tid);
    layer< 8, 7, 55>(B, A, g_Wpad +  93312, b3, sm, tid);
    layer< 7, 5, 37>(A, B, g_Wpad + 114816, b4, sm, tid);
    float* H = B;   // final features: 100 x 37 (cols 37..39 zero)

    // ---- gate = H @ gate_w + gate_b ; softmax over graph; pooled sum
    float gval = -1e30f;
    if (tid < NODES) {
        float s = __ldg(gb);
#pragma unroll
        for (int c = 0; c < 37; c++)
            s += H[tid * ST + c] * __ldg(gw + c);
        sm->gate[tid] = s;
        gval = s;
    }
    if (tid < 128) sm->red[tid] = gval;
    __syncthreads();
    for (int s = 64; s > 0; s >>= 1) {
        if (tid < s) sm->red[tid] = fmaxf(sm->red[tid], sm->red[tid + s]);
        __syncthreads();
    }
    float gmax = sm->red[0];
    __syncthreads();

    float ev = 0.f;
    if (tid < NODES) {
        ev = expf(sm->gate[tid] - gmax);
        sm->gate[tid] = ev;
    }
    if (tid < 128) sm->red[tid] = ev;
    __syncthreads();
    for (int s = 64; s > 0; s >>= 1) {
        if (tid < s) sm->red[tid] += sm->red[tid + s];
        __syncthreads();
    }
    float Z = sm->red[0];

    if (tid < 37) {
        float a = 0.f;
        for (int v = 0; v < NODES; v++)
            a += sm->gate[v] * H[v * ST + tid];
        out[g * 37 + tid] = a / Z;
    }
}

extern "C" void kernel_launch(void* const* d_in, const int* in_sizes, int n_in,
                              void* d_out, int out_size) {
    const float* x   = (const float*)d_in[0];
    const int*   src = (const int*)d_in[1];
    const int*   dst = (const int*)d_in[2];
    const float* W0 = (const float*)d_in[4];
    const float* b0 = (const float*)d_in[5];
    const float* W1 = (const float*)d_in[6];
    const float* b1 = (const float*)d_in[7];
    const float* W2 = (const float*)d_in[8];
    const float* b2 = (const float*)d_in[9];
    const float* W3 = (const float*)d_in[10];
    const float* b3 = (const float*)d_in[11];
    const float* W4 = (const float*)d_in[12];
    const float* b4 = (const float*)d_in[13];
    const float* gw = (const float*)d_in[14];
    const float* gb = (const float*)d_in[15];
    float* out = (float*)d_out;

    prep_weights<<<128, 256>>>(W0, W1, W2, W3, W4);

    const int smem_bytes = (int)sizeof(SmemLayout);
    cudaFuncSetAttribute(gnn_fused_kernel,
                         cudaFuncAttributeMaxDynamicSharedMemorySize,
                         smem_bytes);
    gnn_fused_kernel<<<5000, NTHR, smem_bytes>>>(
        x, src, dst,
        b0, b1, b2, b3, b4,
        gw, gb, out);
}